// round 4
// baseline (speedup 1.0000x reference)
#include <cuda_runtime.h>
#include <cuda_bf16.h>
#include <math.h>

typedef unsigned long long ull;

#define N_TOT 262144
#define GS    64
#define NGRP  (N_TOT / GS)
#define PAD   68

// ---------------- device scratch (no allocations allowed) ----------------
__device__ ull   g_keys[2][N_TOT];
__device__ int   g_ind1[N_TOT];
__device__ int   g_ind2[N_TOT];
__device__ int   g_inv1[N_TOT];
__device__ int   g_ind12[N_TOT];
__device__ float g_x1[(size_t)N_TOT * 64];

// ---------------- Hilbert encode (Skilling), order = 10 ----------------
__device__ __forceinline__ unsigned hilbert3(unsigned X0, unsigned X1, unsigned X2)
{
    const int order = 10;
    for (unsigned Q = 1u << (order - 1); Q > 1; Q >>= 1) {
        unsigned P = Q - 1;
        if (X0 & Q) X0 ^= P;
        unsigned t = (X0 ^ X1) & P;
        if (X1 & Q) { X0 ^= P; } else { X0 ^= t; X1 ^= t; }
        t = (X0 ^ X2) & P;
        if (X2 & Q) { X0 ^= P; } else { X0 ^= t; X2 ^= t; }
    }
    X1 ^= X0;
    X2 ^= X1;
    unsigned t = 0;
    for (unsigned Q = 1u << (order - 1); Q > 1; Q >>= 1)
        if (X2 & Q) t ^= (Q - 1);
    X0 ^= t; X1 ^= t; X2 ^= t;
    unsigned code = 0;
#pragma unroll
    for (int b = order - 1; b >= 0; b--) {
        code = (code << 3) | (((X0 >> b) & 1u) << 2) | (((X1 >> b) & 1u) << 1) | ((X2 >> b) & 1u);
    }
    return code;
}

__global__ void __launch_bounds__(256) codes_kernel(const int* __restrict__ vox_coors)
{
    int i = blockIdx.x * 256 + threadIdx.x;
    if (i >= N_TOT) return;
    int4 v = ((const int4*)vox_coors)[i];
    unsigned b  = (unsigned)v.x;
    unsigned c1 = hilbert3((unsigned)v.y, (unsigned)v.z,      (unsigned)v.w);
    unsigned c2 = hilbert3((unsigned)v.y, (unsigned)v.z + 1u, (unsigned)v.w + 1u);
    // Reference computes keys in int32 (JAX x64 disabled): batch<<30 overflows the
    // sign bit, so signed ascending order = unsigned ascending order of (key ^ 0x80000000).
    unsigned k1 = (((b << 30) | c1) ^ 0x80000000u);
    unsigned k2 = (((b << 30) | c2) ^ 0x80000000u);
    g_keys[0][i] = (((ull)k1) << 32) | (unsigned)i;
    g_keys[1][i] = (((ull)k2) << 32) | (unsigned)i;
}

// ---------------- bitonic sort (uint64 ascending, N = 2^18) ----------------
__global__ void __launch_bounds__(1024) bitonic_local_sort()
{
    __shared__ ull s[4096];
    ull* arr = g_keys[blockIdx.y];
    int base = blockIdx.x * 4096;
    int tid = threadIdx.x;
#pragma unroll
    for (int e = 0; e < 4; e++) s[e * 1024 + tid] = arr[base + e * 1024 + tid];
    __syncthreads();
    for (int k = 2; k <= 4096; k <<= 1) {
        for (int j = k >> 1; j >= 1; j >>= 1) {
#pragma unroll
            for (int e = 0; e < 2; e++) {
                int v = e * 1024 + tid;
                int i = ((v & ~(j - 1)) << 1) | (v & (j - 1));
                int l = i | j;
                bool up = (((unsigned)(base + i)) & (unsigned)k) == 0;
                ull A = s[i], B = s[l];
                if ((A > B) == up) { s[i] = B; s[l] = A; }
            }
            __syncthreads();
        }
    }
#pragma unroll
    for (int e = 0; e < 4; e++) arr[base + e * 1024 + tid] = s[e * 1024 + tid];
}

__global__ void __launch_bounds__(1024) bitonic_local_merge(int k)
{
    __shared__ ull s[4096];
    ull* arr = g_keys[blockIdx.y];
    int base = blockIdx.x * 4096;
    int tid = threadIdx.x;
#pragma unroll
    for (int e = 0; e < 4; e++) s[e * 1024 + tid] = arr[base + e * 1024 + tid];
    __syncthreads();
    bool up = (((unsigned)base) & (unsigned)k) == 0;  // k > 4096 -> constant per chunk
    for (int j = 2048; j >= 1; j >>= 1) {
#pragma unroll
        for (int e = 0; e < 2; e++) {
            int v = e * 1024 + tid;
            int i = ((v & ~(j - 1)) << 1) | (v & (j - 1));
            int l = i | j;
            ull A = s[i], B = s[l];
            if ((A > B) == up) { s[i] = B; s[l] = A; }
        }
        __syncthreads();
    }
#pragma unroll
    for (int e = 0; e < 4; e++) arr[base + e * 1024 + tid] = s[e * 1024 + tid];
}

__global__ void __launch_bounds__(256) bitonic_global(int k, int j)
{
    ull* arr = g_keys[blockIdx.y];
    int v = blockIdx.x * 256 + threadIdx.x;   // 0 .. N/2-1
    int i = ((v & ~(j - 1)) << 1) | (v & (j - 1));
    int l = i | j;
    bool up = (((unsigned)i) & (unsigned)k) == 0;
    ull A = arr[i], B = arr[l];
    if ((A > B) == up) { arr[i] = B; arr[l] = A; }
}

__global__ void __launch_bounds__(256) extract_kernel()
{
    int i = blockIdx.x * 256 + threadIdx.x;
    int i1 = (int)(g_keys[0][i] & 0xffffffffull);
    int i2 = (int)(g_keys[1][i] & 0xffffffffull);
    g_ind1[i] = i1;
    g_ind2[i] = i2;
    g_inv1[i1] = i;
}

__global__ void __launch_bounds__(256) ind12_kernel()
{
    int i = blockIdx.x * 256 + threadIdx.x;
    g_ind12[i] = g_inv1[g_ind2[i]];
}

// ---------------- fused transformer layer ----------------
__device__ __forceinline__ float gelu_tanh(float x)
{
    float x3 = x * x * x;
    float t = tanhf(0.7978845608028654f * (x + 0.044715f * x3));
    return 0.5f * x * (1.0f + t);
}

// layernorm rows of sx[64][PAD] into transposed sxnT[64][PAD]
__device__ __forceinline__ void ln_to_xnT(const float* sx, float* sxnT, int tid)
{
    int lane = tid & 31, w = tid >> 5;
#pragma unroll
    for (int rr = 0; rr < 8; rr++) {
        int r = w * 8 + rr;
        float a = sx[r * PAD + lane];
        float b = sx[r * PAD + lane + 32];
        float s = a + b, q = a * a + b * b;
#pragma unroll
        for (int m = 16; m; m >>= 1) {
            s += __shfl_xor_sync(0xffffffffu, s, m);
            q += __shfl_xor_sync(0xffffffffu, q, m);
        }
        float mean = s * (1.0f / 64.0f);
        float rs = rsqrtf(q * (1.0f / 64.0f) - mean * mean + 1e-5f);
        sxnT[lane * PAD + r]        = (a - mean) * rs;
        sxnT[(lane + 32) * PAD + r] = (b - mean) * rs;
    }
}

#define SMEM_FLOATS (64*PAD /*x*/ + 64*PAD /*xnT,oT*/ + 128*PAD /*qkT*/ + 64*PAD /*v*/ + 256*PAD /*attT,hT*/ + 16384 /*wbuf*/)
#define SMEM_BYTES  (SMEM_FLOATS * 4)

__global__ void __launch_bounds__(256, 1) layer_kernel(
    int layer,
    const float* __restrict__ feats_in, const float* __restrict__ pts,
    const float* __restrict__ wpos, const float* __restrict__ wqkv,
    const float* __restrict__ wo,   const float* __restrict__ wffa,
    const float* __restrict__ wffb, float* __restrict__ dst_out)
{
    extern __shared__ float smf[];
    float* sx    = smf;                    // [64][PAD]
    float* sxnT  = sx    + 64 * PAD;       // [64][PAD]   (also oT)
    float* sqkT  = sxnT  + 64 * PAD;       // [128][PAD]  qT rows 0..63, kT rows 64..127
    float* sv    = sqkT  + 128 * PAD;      // [64][PAD]   v row-major
    float* sattT = sv    + 64 * PAD;       // [256][PAD]  attT (4 heads) / hT
    float* wbuf  = sattT + 256 * PAD;      // 16384 floats

    const float* feats = layer ? g_x1   : feats_in;
    float*       dst   = layer ? dst_out : g_x1;
    const int*   gIdx  = layer ? g_ind12 : g_ind1;
    const int*   pIdx  = layer ? g_ind2  : g_ind1;

    int tid = threadIdx.x;
    int g = blockIdx.x;
    int tr = tid >> 4, tc = tid & 15;

    // stage w_pos (4x64)
    wbuf[tid] = wpos[tid];
    __syncthreads();

    // ---- P0: x = feats[gIdx] + p @ w_pos ----
    {
        int r = tid >> 2;
        int cs = (tid & 3) * 16;
        int gi = gIdx[g * GS + r];
        int pi = pIdx[g * GS + r];
        float4 p = *(const float4*)(pts + (size_t)pi * 4);
#pragma unroll
        for (int cc = 0; cc < 16; cc += 4) {
            int c = cs + cc;
            float4 f  = *(const float4*)(feats + (size_t)gi * 64 + c);
            float4 w0 = *(const float4*)(wbuf + c);
            float4 w1 = *(const float4*)(wbuf + 64 + c);
            float4 w2 = *(const float4*)(wbuf + 128 + c);
            float4 w3 = *(const float4*)(wbuf + 192 + c);
            f.x += p.x * w0.x + p.y * w1.x + p.z * w2.x + p.w * w3.x;
            f.y += p.x * w0.y + p.y * w1.y + p.z * w2.y + p.w * w3.y;
            f.z += p.x * w0.z + p.y * w1.z + p.z * w2.z + p.w * w3.z;
            f.w += p.x * w0.w + p.y * w1.w + p.z * w2.w + p.w * w3.w;
            *(float4*)(sx + r * PAD + c) = f;
        }
    }
    __syncthreads();

    // ---- P1: layernorm -> xnT; stage w_qkv ----
    ln_to_xnT(sx, sxnT, tid);
    {
        float4* wb = (float4*)wbuf;
        const float4* s4 = (const float4*)wqkv;
        for (int i = tid; i < 3072; i += 256) wb[i] = s4[i];
    }
    __syncthreads();

    // ---- P2: qkv = xnT^T @ wqkv ; store qT,kT transposed, v row-major ----
    {
        float acc[3][4][4];
#pragma unroll
        for (int s = 0; s < 3; s++)
#pragma unroll
            for (int i = 0; i < 4; i++)
#pragma unroll
                for (int j = 0; j < 4; j++) acc[s][i][j] = 0.0f;
#pragma unroll 4
        for (int k = 0; k < 64; k++) {
            float4 a = *(float4*)(sxnT + k * PAD + 4 * tr);
            float av[4] = {a.x, a.y, a.z, a.w};
#pragma unroll
            for (int s = 0; s < 3; s++) {
                float4 b = *(float4*)(wbuf + k * 192 + s * 64 + 4 * tc);
#pragma unroll
                for (int i = 0; i < 4; i++) {
                    acc[s][i][0] += av[i] * b.x;
                    acc[s][i][1] += av[i] * b.y;
                    acc[s][i][2] += av[i] * b.z;
                    acc[s][i][3] += av[i] * b.w;
                }
            }
        }
#pragma unroll
        for (int j = 0; j < 4; j++) {
            *(float4*)(sqkT + (4 * tc + j) * PAD + 4 * tr) =
                make_float4(acc[0][0][j], acc[0][1][j], acc[0][2][j], acc[0][3][j]);
            *(float4*)(sqkT + (64 + 4 * tc + j) * PAD + 4 * tr) =
                make_float4(acc[1][0][j], acc[1][1][j], acc[1][2][j], acc[1][3][j]);
        }
#pragma unroll
        for (int i = 0; i < 4; i++) {
            *(float4*)(sv + (4 * tr + i) * PAD + 4 * tc) =
                make_float4(acc[2][i][0], acc[2][i][1], acc[2][i][2], acc[2][i][3]);
        }
    }
    __syncthreads();

    // stage w_o (64x64) — consumed in P3c (sync after P3a covers visibility)
    {
        float4* wb = (float4*)wbuf;
        const float4* s4 = (const float4*)wo;
        for (int i = tid; i < 1024; i += 256) wb[i] = s4[i];
    }

    // ---- P3a: per-head scores + softmax -> attT ----
#pragma unroll 1
    for (int h = 0; h < 4; h++) {
        float s[4][4];
#pragma unroll
        for (int i = 0; i < 4; i++)
#pragma unroll
            for (int j = 0; j < 4; j++) s[i][j] = 0.0f;
#pragma unroll 4
        for (int d = 0; d < 16; d++) {
            float4 af = *(float4*)(sqkT + (16 * h + d) * PAD + 4 * tr);
            float4 bf = *(float4*)(sqkT + (64 + 16 * h + d) * PAD + 4 * tc);
            float av[4] = {af.x, af.y, af.z, af.w};
            float bv[4] = {bf.x, bf.y, bf.z, bf.w};
#pragma unroll
            for (int i = 0; i < 4; i++)
#pragma unroll
                for (int j = 0; j < 4; j++) s[i][j] += av[i] * bv[j];
        }
        float inv[4];
#pragma unroll
        for (int i = 0; i < 4; i++) {
#pragma unroll
            for (int j = 0; j < 4; j++) s[i][j] *= 0.25f;   // 1/sqrt(16)
            float m = fmaxf(fmaxf(s[i][0], s[i][1]), fmaxf(s[i][2], s[i][3]));
#pragma unroll
            for (int msk = 1; msk < 16; msk <<= 1) m = fmaxf(m, __shfl_xor_sync(0xffffffffu, m, msk));
            float sum = 0.0f;
#pragma unroll
            for (int j = 0; j < 4; j++) { s[i][j] = __expf(s[i][j] - m); sum += s[i][j]; }
#pragma unroll
            for (int msk = 1; msk < 16; msk <<= 1) sum += __shfl_xor_sync(0xffffffffu, sum, msk);
            inv[i] = 1.0f / sum;
        }
#pragma unroll
        for (int j = 0; j < 4; j++) {
            *(float4*)(sattT + (h * 64 + 4 * tc + j) * PAD + 4 * tr) =
                make_float4(s[0][j] * inv[0], s[1][j] * inv[1], s[2][j] * inv[2], s[3][j] * inv[3]);
        }
    }
    __syncthreads();

    // ---- P3b: o = att @ v, head-parallel, store transposed into sxnT (oT) ----
    {
        int h = tid >> 6, u = tid & 63;
        int otr = u >> 2, otc = u & 3;
        float o[4][4];
#pragma unroll
        for (int i = 0; i < 4; i++)
#pragma unroll
            for (int j = 0; j < 4; j++) o[i][j] = 0.0f;
#pragma unroll 4
        for (int key = 0; key < 64; key++) {
            float4 af = *(float4*)(sattT + (h * 64 + key) * PAD + 4 * otr);
            float4 bf = *(float4*)(sv + key * PAD + 16 * h + 4 * otc);
            float av[4] = {af.x, af.y, af.z, af.w};
            float bv[4] = {bf.x, bf.y, bf.z, bf.w};
#pragma unroll
            for (int i = 0; i < 4; i++)
#pragma unroll
                for (int j = 0; j < 4; j++) o[i][j] += av[i] * bv[j];
        }
#pragma unroll
        for (int j = 0; j < 4; j++) {
            *(float4*)(sxnT + (16 * h + 4 * otc + j) * PAD + 4 * otr) =
                make_float4(o[0][j], o[1][j], o[2][j], o[3][j]);
        }
    }
    __syncthreads();

    // ---- P3c: x += oT^T @ w_o ----
    {
        float c[4][4];
#pragma unroll
        for (int i = 0; i < 4; i++)
#pragma unroll
            for (int j = 0; j < 4; j++) c[i][j] = 0.0f;
#pragma unroll 4
        for (int k = 0; k < 64; k++) {
            float4 a = *(float4*)(sxnT + k * PAD + 4 * tr);
            float4 b = *(float4*)(wbuf + k * 64 + 4 * tc);
            float av[4] = {a.x, a.y, a.z, a.w};
#pragma unroll
            for (int i = 0; i < 4; i++) {
                c[i][0] += av[i] * b.x; c[i][1] += av[i] * b.y;
                c[i][2] += av[i] * b.z; c[i][3] += av[i] * b.w;
            }
        }
#pragma unroll
        for (int i = 0; i < 4; i++) {
            float4 xv = *(float4*)(sx + (4 * tr + i) * PAD + 4 * tc);
            xv.x += c[i][0]; xv.y += c[i][1]; xv.z += c[i][2]; xv.w += c[i][3];
            *(float4*)(sx + (4 * tr + i) * PAD + 4 * tc) = xv;
        }
    }
    __syncthreads();

    // ---- P4: FF. ln -> xnT; stage w_ffa ----
    ln_to_xnT(sx, sxnT, tid);
    {
        float4* wb = (float4*)wbuf;
        const float4* s4 = (const float4*)wffa;
        for (int i = tid; i < 4096; i += 256) wb[i] = s4[i];
    }
    __syncthreads();

    // gemm1: h = gelu(xnT^T @ wffa) -> hT (in sattT)
    {
        float acc[4][4][4];
#pragma unroll
        for (int s = 0; s < 4; s++)
#pragma unroll
            for (int i = 0; i < 4; i++)
#pragma unroll
                for (int j = 0; j < 4; j++) acc[s][i][j] = 0.0f;
#pragma unroll 2
        for (int k = 0; k < 64; k++) {
            float4 a = *(float4*)(sxnT + k * PAD + 4 * tr);
            float av[4] = {a.x, a.y, a.z, a.w};
#pragma unroll
            for (int s = 0; s < 4; s++) {
                float4 b = *(float4*)(wbuf + k * 256 + s * 64 + 4 * tc);
#pragma unroll
                for (int i = 0; i < 4; i++) {
                    acc[s][i][0] += av[i] * b.x;
                    acc[s][i][1] += av[i] * b.y;
                    acc[s][i][2] += av[i] * b.z;
                    acc[s][i][3] += av[i] * b.w;
                }
            }
        }
#pragma unroll
        for (int s = 0; s < 4; s++)
#pragma unroll
            for (int j = 0; j < 4; j++) {
                *(float4*)(sattT + (64 * s + 4 * tc + j) * PAD + 4 * tr) =
                    make_float4(gelu_tanh(acc[s][0][j]), gelu_tanh(acc[s][1][j]),
                                gelu_tanh(acc[s][2][j]), gelu_tanh(acc[s][3][j]));
            }
    }
    __syncthreads();

    // stage w_ffb
    {
        float4* wb = (float4*)wbuf;
        const float4* s4 = (const float4*)wffb;
        for (int i = tid; i < 4096; i += 256) wb[i] = s4[i];
    }
    __syncthreads();

    // gemm2: x += hT^T @ wffb ; write out
    {
        float c[4][4];
#pragma unroll
        for (int i = 0; i < 4; i++)
#pragma unroll
            for (int j = 0; j < 4; j++) c[i][j] = 0.0f;
#pragma unroll 4
        for (int k = 0; k < 256; k++) {
            float4 a = *(float4*)(sattT + k * PAD + 4 * tr);
            float4 b = *(float4*)(wbuf + k * 64 + 4 * tc);
            float av[4] = {a.x, a.y, a.z, a.w};
#pragma unroll
            for (int i = 0; i < 4; i++) {
                c[i][0] += av[i] * b.x; c[i][1] += av[i] * b.y;
                c[i][2] += av[i] * b.z; c[i][3] += av[i] * b.w;
            }
        }
#pragma unroll
        for (int i = 0; i < 4; i++) {
            float4 xv = *(float4*)(sx + (4 * tr + i) * PAD + 4 * tc);
            xv.x += c[i][0]; xv.y += c[i][1]; xv.z += c[i][2]; xv.w += c[i][3];
            *(float4*)(dst + ((size_t)(g * GS + 4 * tr + i)) * 64 + 4 * tc) = xv;
        }
    }
}

// ---------------- launch ----------------
extern "C" void kernel_launch(void* const* d_in, const int* in_sizes, int n_in,
                              void* d_out, int out_size)
{
    const float* vox_feats = (const float*)d_in[0];
    const float* pts_coors = (const float*)d_in[1];
    const int*   vox_coors = (const int*)d_in[2];
    const float* w[10];
    for (int i = 0; i < 10; i++) w[i] = (const float*)d_in[n_in - 10 + i];
    float* out = (float*)d_out;

    cudaFuncSetAttribute(layer_kernel, cudaFuncAttributeMaxDynamicSharedMemorySize, SMEM_BYTES);

    codes_kernel<<<N_TOT / 256, 256>>>(vox_coors);

    dim3 gl(64, 2);
    bitonic_local_sort<<<gl, 1024>>>();
    for (int k = 8192; k <= N_TOT; k <<= 1) {
        for (int j = k >> 1; j >= 4096; j >>= 1)
            bitonic_global<<<dim3(512, 2), 256>>>(k, j);
        bitonic_local_merge<<<gl, 1024>>>(k);
    }

    extract_kernel<<<N_TOT / 256, 256>>>();
    ind12_kernel<<<N_TOT / 256, 256>>>();

    layer_kernel<<<NGRP, 256, SMEM_BYTES>>>(0, vox_feats, pts_coors,
                                            w[0], w[1], w[2], w[3], w[4], out);
    layer_kernel<<<NGRP, 256, SMEM_BYTES>>>(1, vox_feats, pts_coors,
                                            w[5], w[6], w[7], w[8], w[9], out);
}

// round 6
// speedup vs baseline: 1.1794x; 1.1794x over previous
#include <cuda_runtime.h>
#include <cuda_bf16.h>
#include <math.h>

typedef unsigned long long ull;

#define N_TOT 262144
#define GS    64
#define NGRP  (N_TOT / GS)
#define PAD   68
#define HST   132
#define WST   72
#define WSTA  136

// ---------------- device scratch (no allocations allowed) ----------------
__device__ ull   g_keys[2][N_TOT];
__device__ int   g_ind1[N_TOT];
__device__ int   g_ind2[N_TOT];
__device__ int   g_inv1[N_TOT];
__device__ int   g_ind12[N_TOT];
__device__ float g_x1[(size_t)N_TOT * 64];

// ---------------- Hilbert encode (Skilling), order = 10 ----------------
__device__ __forceinline__ unsigned hilbert3(unsigned X0, unsigned X1, unsigned X2)
{
    const int order = 10;
    for (unsigned Q = 1u << (order - 1); Q > 1; Q >>= 1) {
        unsigned P = Q - 1;
        if (X0 & Q) X0 ^= P;
        unsigned t = (X0 ^ X1) & P;
        if (X1 & Q) { X0 ^= P; } else { X0 ^= t; X1 ^= t; }
        t = (X0 ^ X2) & P;
        if (X2 & Q) { X0 ^= P; } else { X0 ^= t; X2 ^= t; }
    }
    X1 ^= X0;
    X2 ^= X1;
    unsigned t = 0;
    for (unsigned Q = 1u << (order - 1); Q > 1; Q >>= 1)
        if (X2 & Q) t ^= (Q - 1);
    X0 ^= t; X1 ^= t; X2 ^= t;
    unsigned code = 0;
#pragma unroll
    for (int b = order - 1; b >= 0; b--) {
        code = (code << 3) | (((X0 >> b) & 1u) << 2) | (((X1 >> b) & 1u) << 1) | ((X2 >> b) & 1u);
    }
    return code;
}

__global__ void __launch_bounds__(256) codes_kernel(const int* __restrict__ vox_coors)
{
    int i = blockIdx.x * 256 + threadIdx.x;
    if (i >= N_TOT) return;
    int4 v = ((const int4*)vox_coors)[i];
    unsigned b  = (unsigned)v.x;
    unsigned c1 = hilbert3((unsigned)v.y, (unsigned)v.z,      (unsigned)v.w);
    unsigned c2 = hilbert3((unsigned)v.y, (unsigned)v.z + 1u, (unsigned)v.w + 1u);
    // Reference computes keys in int32 (JAX x64 disabled): batch<<30 overflows the
    // sign bit, so signed ascending order = unsigned ascending order of (key ^ 0x80000000).
    unsigned k1 = (((b << 30) | c1) ^ 0x80000000u);
    unsigned k2 = (((b << 30) | c2) ^ 0x80000000u);
    g_keys[0][i] = (((ull)k1) << 32) | (unsigned)i;
    g_keys[1][i] = (((ull)k2) << 32) | (unsigned)i;
}

// ---------------- bitonic sort (uint64 ascending, N = 2^18) ----------------
__global__ void __launch_bounds__(1024) bitonic_local_sort()
{
    __shared__ ull s[4096];
    ull* arr = g_keys[blockIdx.y];
    int base = blockIdx.x * 4096;
    int tid = threadIdx.x;
#pragma unroll
    for (int e = 0; e < 4; e++) s[e * 1024 + tid] = arr[base + e * 1024 + tid];
    __syncthreads();
    for (int k = 2; k <= 4096; k <<= 1) {
        for (int j = k >> 1; j >= 1; j >>= 1) {
#pragma unroll
            for (int e = 0; e < 2; e++) {
                int v = e * 1024 + tid;
                int i = ((v & ~(j - 1)) << 1) | (v & (j - 1));
                int l = i | j;
                bool up = (((unsigned)(base + i)) & (unsigned)k) == 0;
                ull A = s[i], B = s[l];
                if ((A > B) == up) { s[i] = B; s[l] = A; }
            }
            __syncthreads();
        }
    }
#pragma unroll
    for (int e = 0; e < 4; e++) arr[base + e * 1024 + tid] = s[e * 1024 + tid];
}

__global__ void __launch_bounds__(1024) bitonic_local_merge(int k)
{
    __shared__ ull s[4096];
    ull* arr = g_keys[blockIdx.y];
    int base = blockIdx.x * 4096;
    int tid = threadIdx.x;
#pragma unroll
    for (int e = 0; e < 4; e++) s[e * 1024 + tid] = arr[base + e * 1024 + tid];
    __syncthreads();
    bool up = (((unsigned)base) & (unsigned)k) == 0;  // k > 4096 -> constant per chunk
    for (int j = 2048; j >= 1; j >>= 1) {
#pragma unroll
        for (int e = 0; e < 2; e++) {
            int v = e * 1024 + tid;
            int i = ((v & ~(j - 1)) << 1) | (v & (j - 1));
            int l = i | j;
            ull A = s[i], B = s[l];
            if ((A > B) == up) { s[i] = B; s[l] = A; }
        }
        __syncthreads();
    }
#pragma unroll
    for (int e = 0; e < 4; e++) arr[base + e * 1024 + tid] = s[e * 1024 + tid];
}

__global__ void __launch_bounds__(256) bitonic_global(int k, int j)
{
    ull* arr = g_keys[blockIdx.y];
    int v = blockIdx.x * 256 + threadIdx.x;   // 0 .. N/2-1
    int i = ((v & ~(j - 1)) << 1) | (v & (j - 1));
    int l = i | j;
    bool up = (((unsigned)i) & (unsigned)k) == 0;
    ull A = arr[i], B = arr[l];
    if ((A > B) == up) { arr[i] = B; arr[l] = A; }
}

__global__ void __launch_bounds__(256) extract_kernel()
{
    int i = blockIdx.x * 256 + threadIdx.x;
    int i1 = (int)(g_keys[0][i] & 0xffffffffull);
    int i2 = (int)(g_keys[1][i] & 0xffffffffull);
    g_ind1[i] = i1;
    g_ind2[i] = i2;
    g_inv1[i1] = i;
}

__global__ void __launch_bounds__(256) ind12_kernel()
{
    int i = blockIdx.x * 256 + threadIdx.x;
    g_ind12[i] = g_inv1[g_ind2[i]];
}

// ---------------- tf32 helpers ----------------
__device__ __forceinline__ float tf32r(float x)
{
    unsigned u;
    asm("cvt.rna.tf32.f32 %0, %1;" : "=r"(u) : "f"(x));
    return __uint_as_float(u);
}

// m16n8k4 tf32 mma: D += A(16x4) * B(4x8).
// A: a0=(row g, col t), a1=(row g+8, col t); B: b0=(k t, col g);
// D: c0=(g,2t) c1=(g,2t+1) c2=(g+8,2t) c3=(g+8,2t+1).  (g=lane>>2, t=lane&3)
__device__ __forceinline__ void mma4(float4& d, float a0, float a1, float b0)
{
    asm volatile("mma.sync.aligned.m16n8k4.row.col.f32.tf32.tf32.f32 "
                 "{%0,%1,%2,%3}, {%4,%5}, {%6}, {%0,%1,%2,%3};"
                 : "+f"(d.x), "+f"(d.y), "+f"(d.z), "+f"(d.w)
                 : "r"(__float_as_uint(a0)), "r"(__float_as_uint(a1)),
                   "r"(__float_as_uint(b0)));
}

__device__ __forceinline__ void load_afrag(const float* A, int stride, int mrow,
                                           int gid, int tig, int koff,
                                           float* a0, float* a1)
{
#pragma unroll
    for (int ks = 0; ks < 16; ks++) {
        a0[ks] = A[(mrow + gid) * stride + koff + 4 * ks + tig];
        a1[ks] = A[(mrow + gid + 8) * stride + koff + 4 * ks + tig];
    }
}

__device__ __forceinline__ float gelu_tanh(float x)
{
    float x3 = x * x * x;
    float t = tanhf(0.7978845608028654f * (x + 0.044715f * x3));
    return 0.5f * x * (1.0f + t);
}

// layernorm rows of sx[64][PAD] -> row-major tf32-rounded sxn[64][PAD]
__device__ __forceinline__ void ln_rows(const float* sx, float* sxn, int tid)
{
    int lane = tid & 31, w = tid >> 5;
#pragma unroll
    for (int rr = 0; rr < 8; rr++) {
        int r = w * 8 + rr;
        float a = sx[r * PAD + lane];
        float b = sx[r * PAD + lane + 32];
        float s = a + b, q = a * a + b * b;
#pragma unroll
        for (int m = 16; m; m >>= 1) {
            s += __shfl_xor_sync(0xffffffffu, s, m);
            q += __shfl_xor_sync(0xffffffffu, q, m);
        }
        float mean = s * (1.0f / 64.0f);
        float rs = rsqrtf(q * (1.0f / 64.0f) - mean * mean + 1e-5f);
        sxn[r * PAD + lane]      = tf32r((a - mean) * rs);
        sxn[r * PAD + lane + 32] = tf32r((b - mean) * rs);
    }
}

// smem: sx 64*68 | sxn 64*68 | sqkT 128*68 | sv 64*68 | sattT 256*68 | sh 64*132 | wbuf 9216
#define SMEM_FLOATS (64*PAD + 64*PAD + 128*PAD + 64*PAD + 256*PAD + 64*HST + 9216)
#define SMEM_BYTES  (SMEM_FLOATS * 4)

__global__ void __launch_bounds__(256, 1) layer_kernel(
    int layer,
    const float* __restrict__ feats_in, const float* __restrict__ pts,
    const float* __restrict__ wpos, const float* __restrict__ wqkv,
    const float* __restrict__ wo,   const float* __restrict__ wffa,
    const float* __restrict__ wffb, float* __restrict__ dst_out)
{
    extern __shared__ float smf[];
    float* sx    = smf;                    // [64][PAD] residual stream (fp32)
    float* sxn   = sx    + 64 * PAD;       // [64][PAD] ln out (tf32) / o (tf32)
    float* sqkT  = sxn   + 64 * PAD;       // [128][PAD] qT rows 0..63, kT rows 64..127
    float* sv    = sqkT  + 128 * PAD;      // [64][PAD]  v row-major
    float* sattT = sv    + 64 * PAD;       // [256][PAD] att (4 heads, key-major)
    float* sh    = sattT + 256 * PAD;      // [64][HST]  ff hidden half (tf32)
    float* wbuf  = sh    + 64 * HST;       // 9216 floats, staged weights (tf32)

    const float* feats = layer ? g_x1   : feats_in;
    float*       dst   = layer ? dst_out : g_x1;
    const int*   gIdx  = layer ? g_ind12 : g_ind1;
    const int*   pIdx  = layer ? g_ind2  : g_ind1;

    int tid = threadIdx.x;
    int g = blockIdx.x;
    int lane = tid & 31, w = tid >> 5;
    int gid = lane >> 2, tig = lane & 3;
    int mrow = 16 * (w & 3), qh = w >> 2;
    int tr = tid >> 4, tc = tid & 15;

    float a0[16], a1[16];

    // stage w_pos (4x64, fp32)
    wbuf[tid] = wpos[tid];
    __syncthreads();

    // ---- P0: x = feats[gIdx] + p @ w_pos ----
    {
        int r = tid >> 2;
        int cs = (tid & 3) * 16;
        int gi = gIdx[g * GS + r];
        int pi = pIdx[g * GS + r];
        float4 p = *(const float4*)(pts + (size_t)pi * 4);
#pragma unroll
        for (int cc = 0; cc < 16; cc += 4) {
            int c = cs + cc;
            float4 f  = *(const float4*)(feats + (size_t)gi * 64 + c);
            float4 w0 = *(const float4*)(wbuf + c);
            float4 w1 = *(const float4*)(wbuf + 64 + c);
            float4 w2 = *(const float4*)(wbuf + 128 + c);
            float4 w3 = *(const float4*)(wbuf + 192 + c);
            f.x += p.x * w0.x + p.y * w1.x + p.z * w2.x + p.w * w3.x;
            f.y += p.x * w0.y + p.y * w1.y + p.z * w2.y + p.w * w3.y;
            f.z += p.x * w0.z + p.y * w1.z + p.z * w2.z + p.w * w3.z;
            f.w += p.x * w0.w + p.y * w1.w + p.z * w2.w + p.w * w3.w;
            *(float4*)(sx + r * PAD + c) = f;
        }
    }
    __syncthreads();

    // ---- P1: layernorm -> xn (row-major, tf32) ----
    ln_rows(sx, sxn, tid);
    __syncthreads();

    // ---- P2: q/k/v GEMMs via tf32 mma, weights staged in thirds ----
    load_afrag(sxn, PAD, mrow, gid, tig, 0, a0, a1);
#pragma unroll 1
    for (int s = 0; s < 3; s++) {
        for (int i = tid; i < 4096; i += 256)
            wbuf[(i >> 6) * WST + (i & 63)] = tf32r(wqkv[(i >> 6) * 192 + s * 64 + (i & 63)]);
        __syncthreads();
#pragma unroll
        for (int t = 0; t < 4; t++) {
            int nb = (qh * 4 + t) * 8;
            float4 acc = make_float4(0.f, 0.f, 0.f, 0.f);
#pragma unroll
            for (int ks = 0; ks < 16; ks++)
                mma4(acc, a0[ks], a1[ks], wbuf[(4 * ks + tig) * WST + nb + gid]);
            int n0 = nb + 2 * tig, r0 = mrow + gid;
            if (s < 2) {   // q, k stored transposed for SIMT attention
                int ro = s * 64;
                sqkT[(ro + n0) * PAD + r0]         = acc.x;
                sqkT[(ro + n0 + 1) * PAD + r0]     = acc.y;
                sqkT[(ro + n0) * PAD + r0 + 8]     = acc.z;
                sqkT[(ro + n0 + 1) * PAD + r0 + 8] = acc.w;
            } else {       // v row-major
                *(float2*)(sv + r0 * PAD + n0)       = make_float2(acc.x, acc.y);
                *(float2*)(sv + (r0 + 8) * PAD + n0) = make_float2(acc.z, acc.w);
            }
        }
        __syncthreads();
    }

    // stage w_o (64x64) — consumed in P3c; P3a/P3b syncs cover visibility
    for (int i = tid; i < 4096; i += 256)
        wbuf[(i >> 6) * WST + (i & 63)] = tf32r(wo[i]);

    // ---- P3a: per-head scores + softmax -> sattT (SIMT fp32) ----
#pragma unroll 1
    for (int h = 0; h < 4; h++) {
        float s[4][4];
#pragma unroll
        for (int i = 0; i < 4; i++)
#pragma unroll
            for (int j = 0; j < 4; j++) s[i][j] = 0.0f;
#pragma unroll 4
        for (int d = 0; d < 16; d++) {
            float4 af = *(float4*)(sqkT + (16 * h + d) * PAD + 4 * tr);
            float4 bf = *(float4*)(sqkT + (64 + 16 * h + d) * PAD + 4 * tc);
            float av[4] = {af.x, af.y, af.z, af.w};
            float bv[4] = {bf.x, bf.y, bf.z, bf.w};
#pragma unroll
            for (int i = 0; i < 4; i++)
#pragma unroll
                for (int j = 0; j < 4; j++) s[i][j] += av[i] * bv[j];
        }
        float inv[4];
#pragma unroll
        for (int i = 0; i < 4; i++) {
#pragma unroll
            for (int j = 0; j < 4; j++) s[i][j] *= 0.25f;   // 1/sqrt(16)
            float m = fmaxf(fmaxf(s[i][0], s[i][1]), fmaxf(s[i][2], s[i][3]));
#pragma unroll
            for (int msk = 1; msk < 16; msk <<= 1) m = fmaxf(m, __shfl_xor_sync(0xffffffffu, m, msk));
            float sum = 0.0f;
#pragma unroll
            for (int j = 0; j < 4; j++) { s[i][j] = __expf(s[i][j] - m); sum += s[i][j]; }
#pragma unroll
            for (int msk = 1; msk < 16; msk <<= 1) sum += __shfl_xor_sync(0xffffffffu, sum, msk);
            inv[i] = 1.0f / sum;
        }
#pragma unroll
        for (int j = 0; j < 4; j++) {
            *(float4*)(sattT + (h * 64 + 4 * tc + j) * PAD + 4 * tr) =
                make_float4(s[0][j] * inv[0], s[1][j] * inv[1], s[2][j] * inv[2], s[3][j] * inv[3]);
        }
    }
    __syncthreads();

    // ---- P3b: o = att @ v, head-parallel; store o row-major tf32 into sxn ----
    {
        int hh = tid >> 6, u = tid & 63;
        int otr = u >> 2, otc = u & 3;
        float o[4][4];
#pragma unroll
        for (int i = 0; i < 4; i++)
#pragma unroll
            for (int j = 0; j < 4; j++) o[i][j] = 0.0f;
#pragma unroll 4
        for (int key = 0; key < 64; key++) {
            float4 af = *(float4*)(sattT + (hh * 64 + key) * PAD + 4 * otr);
            float4 bf = *(float4*)(sv + key * PAD + 16 * hh + 4 * otc);
            float av[4] = {af.x, af.y, af.z, af.w};
            float bv[4] = {bf.x, bf.y, bf.z, bf.w};
#pragma unroll
            for (int i = 0; i < 4; i++)
#pragma unroll
                for (int j = 0; j < 4; j++) o[i][j] += av[i] * bv[j];
        }
#pragma unroll
        for (int i = 0; i < 4; i++) {
            *(float4*)(sxn + (4 * otr + i) * PAD + 16 * hh + 4 * otc) =
                make_float4(tf32r(o[i][0]), tf32r(o[i][1]), tf32r(o[i][2]), tf32r(o[i][3]));
        }
    }
    __syncthreads();

    // ---- P3c: x += o @ w_o (tf32 mma) ----
    load_afrag(sxn, PAD, mrow, gid, tig, 0, a0, a1);
#pragma unroll
    for (int t = 0; t < 4; t++) {
        int nb = (qh * 4 + t) * 8;
        float4 acc = make_float4(0.f, 0.f, 0.f, 0.f);
#pragma unroll
        for (int ks = 0; ks < 16; ks++)
            mma4(acc, a0[ks], a1[ks], wbuf[(4 * ks + tig) * WST + nb + gid]);
        int n0 = nb + 2 * tig, r0 = mrow + gid;
        sx[r0 * PAD + n0]           += acc.x;
        sx[r0 * PAD + n0 + 1]       += acc.y;
        sx[(r0 + 8) * PAD + n0]     += acc.z;
        sx[(r0 + 8) * PAD + n0 + 1] += acc.w;
    }
    __syncthreads();

    // ---- P4: FF. ln -> xn; ffa/ffb in halves, ffb accum in registers ----
    ln_rows(sx, sxn, tid);
    float4 accB[4];
#pragma unroll
    for (int t = 0; t < 4; t++) accB[t] = make_float4(0.f, 0.f, 0.f, 0.f);

#pragma unroll 1
    for (int half = 0; half < 2; half++) {
        __syncthreads();   // xn ready (half 0) / prev ffb done reading wbuf (half 1)
        for (int i = tid; i < 8192; i += 256)
            wbuf[(i >> 7) * WSTA + (i & 127)] =
                tf32r(wffa[(i >> 7) * 256 + half * 128 + (i & 127)]);
        __syncthreads();

        // ffa half: h = gelu(xn @ wffa[:, half]) (tf32 out)
        load_afrag(sxn, PAD, mrow, gid, tig, 0, a0, a1);
#pragma unroll
        for (int t = 0; t < 8; t++) {
            int nb = (qh * 8 + t) * 8;
            float4 acc = make_float4(0.f, 0.f, 0.f, 0.f);
#pragma unroll
            for (int ks = 0; ks < 16; ks++)
                mma4(acc, a0[ks], a1[ks], wbuf[(4 * ks + tig) * WSTA + nb + gid]);
            int n0 = nb + 2 * tig, r0 = mrow + gid;
            *(float2*)(sh + r0 * HST + n0) =
                make_float2(tf32r(gelu_tanh(acc.x)), tf32r(gelu_tanh(acc.y)));
            *(float2*)(sh + (r0 + 8) * HST + n0) =
                make_float2(tf32r(gelu_tanh(acc.z)), tf32r(gelu_tanh(acc.w)));
        }
        __syncthreads();

        // stage wffb rows [half*128, half*128+128)
        for (int i = tid; i < 8192; i += 256)
            wbuf[(i >> 6) * WST + (i & 63)] =
                tf32r(wffb[(half * 128 + (i >> 6)) * 64 + (i & 63)]);
        __syncthreads();

        // ffb: accB += h @ wffb_half  (K=128 per half, 2 chunks of 16 k4-steps)
#pragma unroll 1
        for (int c = 0; c < 2; c++) {
            load_afrag(sh, HST, mrow, gid, tig, 64 * c, a0, a1);
#pragma unroll
            for (int t = 0; t < 4; t++) {
                int nb = (qh * 4 + t) * 8;
#pragma unroll
                for (int ks = 0; ks < 16; ks++)
                    mma4(accB[t], a0[ks], a1[ks],
                         wbuf[(4 * (16 * c + ks) + tig) * WST + nb + gid]);
            }
        }
    }

    // ---- write out: dst = x + ff ----
#pragma unroll
    for (int t = 0; t < 4; t++) {
        int nb = (qh * 4 + t) * 8, n0 = nb + 2 * tig, r0 = mrow + gid;
        float2 lo = make_float2(sx[r0 * PAD + n0] + accB[t].x,
                                sx[r0 * PAD + n0 + 1] + accB[t].y);
        float2 hi = make_float2(sx[(r0 + 8) * PAD + n0] + accB[t].z,
                                sx[(r0 + 8) * PAD + n0 + 1] + accB[t].w);
        *(float2*)(dst + (size_t)(g * GS + r0) * 64 + n0)     = lo;
        *(float2*)(dst + (size_t)(g * GS + r0 + 8) * 64 + n0) = hi;
    }
}

// ---------------- launch ----------------
extern "C" void kernel_launch(void* const* d_in, const int* in_sizes, int n_in,
                              void* d_out, int out_size)
{
    const float* vox_feats = (const float*)d_in[0];
    const float* pts_coors = (const float*)d_in[1];
    const int*   vox_coors = (const int*)d_in[2];
    const float* w[10];
    for (int i = 0; i < 10; i++) w[i] = (const float*)d_in[n_in - 10 + i];
    float* out = (float*)d_out;

    cudaFuncSetAttribute(layer_kernel, cudaFuncAttributeMaxDynamicSharedMemorySize, SMEM_BYTES);

    codes_kernel<<<N_TOT / 256, 256>>>(vox_coors);

    dim3 gl(64, 2);
    bitonic_local_sort<<<gl, 1024>>>();
    for (int k = 8192; k <= N_TOT; k <<= 1) {
        for (int j = k >> 1; j >= 4096; j >>= 1)
            bitonic_global<<<dim3(512, 2), 256>>>(k, j);
        bitonic_local_merge<<<gl, 1024>>>(k);
    }

    extract_kernel<<<N_TOT / 256, 256>>>();
    ind12_kernel<<<N_TOT / 256, 256>>>();

    layer_kernel<<<NGRP, 256, SMEM_BYTES>>>(0, vox_feats, pts_coors,
                                            w[0], w[1], w[2], w[3], w[4], out);
    layer_kernel<<<NGRP, 256, SMEM_BYTES>>>(1, vox_feats, pts_coors,
                                            w[5], w[6], w[7], w[8], w[9], out);
}